// round 1
// baseline (speedup 1.0000x reference)
#include <cuda_runtime.h>

#define CH 6
#define MODES 16
#define BB 32
#define NPT 65536
#define NMASK 65535
#define TSTEPS 8

#define TILE 2048
#define HALO 4
#define EXT (TILE + 2*HALO)      // 2056
#define RKTHREADS 256
#define FBLK 8                   // blocks per (b,i) in forward DFT

// -------- scratch (no allocations allowed) --------
__device__ float g_bufA[BB*CH*NPT];
__device__ float g_bufB[BB*CH*NPT];
__device__ float g_part[BB*CH*FBLK*MODES*2];
__device__ float g_Z[BB*CH*MODES*2];

__device__ __forceinline__ float fast_tanh(float x){
    // accurate to ~1e-6 abs; clamp kills NaN garbage from halo slots too
    float xc = fminf(fmaxf(x, -9.0f), 9.0f);
    float e  = __expf(2.0f*xc);
    return __fdividef(e - 1.0f, e + 1.0f);
}

// ---------------- RK4 step kernel ----------------
// One kernel = one full RK4 step (4 conv+tanh stages), tile+halo in SMEM.
// Stage s computed on positions [1, EXT-1); validity shrinks 1/side per stage;
// combine uses only central [HALO, EXT-HALO) which stays valid.

template<bool USEK>
__device__ __forceinline__ void conv_stage(
    const float* __restrict__ su, const float* __restrict__ kin,
    float* __restrict__ kout,
    const float* __restrict__ sw, const float* __restrict__ sb,
    float c, float aw, int gofs, int tid,
    float acc[CH][8], float acct[CH])
{
    const int base = 1 + tid*8;                 // main chunk [base, base+8) in [1,2049)
    float a[CH][8];
    #pragma unroll
    for (int co=0; co<CH; co++)
        #pragma unroll
        for (int j=0; j<8; j++) a[co][j] = 0.f;

    #pragma unroll
    for (int ci=0; ci<CH; ci++){
        float xv[10];
        #pragma unroll
        for (int j=0; j<10; j++){
            int p = base - 1 + j;
            float v;
            if (USEK) v = fmaf(c, kin[ci*EXT+p], su[ci*EXT+p]);
            else      v = su[ci*EXT+p];
            int g = gofs + p;
            xv[j] = ((unsigned)g < NPT) ? v : 0.f;   // conv zero-padding at global edges
        }
        #pragma unroll
        for (int co=0; co<CH; co++){
            float w0 = sw[(co*CH+ci)*3 + 0];
            float w1 = sw[(co*CH+ci)*3 + 1];
            float w2 = sw[(co*CH+ci)*3 + 2];
            #pragma unroll
            for (int j=0; j<8; j++)
                a[co][j] = fmaf(w0, xv[j], fmaf(w1, xv[j+1], fmaf(w2, xv[j+2], a[co][j])));
        }
    }
    #pragma unroll
    for (int co=0; co<CH; co++){
        float bias = sb[co];
        #pragma unroll
        for (int j=0; j<8; j++){
            float t = fast_tanh(a[co][j] + bias);
            kout[co*EXT + base + j] = t;
            if (base + j >= HALO)                    // central accumulate (p < EXT-HALO always here)
                acc[co][j] = fmaf(aw, t, acc[co][j]);
        }
    }
    // tail positions [2049, 2055): one per thread for tid<6
    if (tid < 6){
        int p = 1 + RKTHREADS*8 + tid;
        #pragma unroll
        for (int co=0; co<CH; co++){
            float s = 0.f;
            #pragma unroll
            for (int ci=0; ci<CH; ci++){
                #pragma unroll
                for (int t3=0; t3<3; t3++){
                    int pp = p - 1 + t3;
                    float v;
                    if (USEK) v = fmaf(c, kin[ci*EXT+pp], su[ci*EXT+pp]);
                    else      v = su[ci*EXT+pp];
                    int g = gofs + pp;
                    v = ((unsigned)g < NPT) ? v : 0.f;
                    s = fmaf(sw[(co*CH+ci)*3 + t3], v, s);
                }
            }
            float t = fast_tanh(s + sb[co]);
            kout[co*EXT + p] = t;
            if (p < EXT - HALO)
                acct[co] = fmaf(aw, t, acct[co]);
        }
    }
}

__global__ void __launch_bounds__(RKTHREADS, 1)
rk4_kernel(const float* __restrict__ src, float* __restrict__ dst,
           const float* __restrict__ t_span, int step,
           const float* __restrict__ conv_w, const float* __restrict__ conv_b)
{
    extern __shared__ float smem[];
    float* su = smem;                 // CH*EXT
    float* ka = su + CH*EXT;
    float* kb = ka + CH*EXT;
    float* sw = kb + CH*EXT;          // 108
    float* sb = sw + CH*CH*3;         // 6

    const int b     = blockIdx.y;
    const int tile0 = blockIdx.x * TILE;
    const int gofs  = tile0 - HALO;
    const int tid   = threadIdx.x;

    float dt = t_span[step+1] - t_span[step];

    if (tid < CH*CH*3) sw[tid] = conv_w[tid];
    if (tid < CH)      sb[tid] = conv_b[tid];

    #pragma unroll
    for (int ch=0; ch<CH; ch++){
        const float* sc = src + ((size_t)b*CH + ch)*NPT;
        for (int p=tid; p<EXT; p+=RKTHREADS){
            int g = gofs + p;
            su[ch*EXT+p] = ((unsigned)g < NPT) ? sc[g] : 0.f;
        }
    }
    __syncthreads();

    float acc[CH][8];
    float acct[CH];
    #pragma unroll
    for (int co=0; co<CH; co++){
        acct[co] = 0.f;
        #pragma unroll
        for (int j=0; j<8; j++) acc[co][j] = 0.f;
    }

    conv_stage<false>(su, ka, ka, sw, sb, 0.f,      1.f, gofs, tid, acc, acct);
    __syncthreads();
    conv_stage<true >(su, ka, kb, sw, sb, 0.5f*dt,  2.f, gofs, tid, acc, acct);
    __syncthreads();
    conv_stage<true >(su, kb, ka, sw, sb, 0.5f*dt,  2.f, gofs, tid, acc, acct);
    __syncthreads();
    conv_stage<true >(su, ka, kb, sw, sb, dt,       1.f, gofs, tid, acc, acct);

    const float dt6 = dt * (1.0f/6.0f);
    const int base = 1 + tid*8;
    #pragma unroll
    for (int co=0; co<CH; co++){
        float* dc_ = dst + ((size_t)b*CH + co)*NPT;
        #pragma unroll
        for (int j=0; j<8; j++){
            int p = base + j;
            if (p >= HALO)
                dc_[gofs + p] = su[co*EXT+p] + dt6 * acc[co][j];
        }
    }
    if (tid < 3){
        int p = 1 + RKTHREADS*8 + tid;   // 2049..2051, central since < 2052
        #pragma unroll
        for (int co=0; co<CH; co++)
            dst[((size_t)b*CH + co)*NPT + gofs + p] = su[co*EXT+p] + dt6 * acct[co];
    }
}

// ---------------- forward 16-mode DFT (partial sums) ----------------
__global__ void __launch_bounds__(256)
fwd_dft_kernel(const float* __restrict__ u)
{
    const int blk  = blockIdx.x;                 // [0, BB*CH*FBLK)
    const int seg  = blk & (FBLK-1);
    const int bi   = blk / FBLK;                 // b*CH + i
    const int tid  = threadIdx.x;
    const int lane = tid & 31, warp = tid >> 5;
    const int n0   = seg*8192 + warp*1024 + lane;  // stride-32 walk, coalesced
    const float* x = u + (size_t)bi*NPT;

    const float TWO_PI = 6.283185307179586f;
    float cr[MODES], cim[MODES], ck[MODES], sk[MODES], dc[MODES], ds[MODES];
    #pragma unroll
    for (int k=0; k<MODES; k++){
        cr[k]=0.f; cim[k]=0.f;
        float a0 = TWO_PI * ((float)((k*n0) & NMASK) * (1.0f/NPT));
        sincosf(a0, &sk[k], &ck[k]);
        float ad = TWO_PI * ((float)(k*32) * (1.0f/NPT));
        sincosf(ad, &ds[k], &dc[k]);
    }
    #pragma unroll 2
    for (int j=0; j<32; j++){
        float v = __ldg(&x[n0 + (j<<5)]);
        #pragma unroll
        for (int k=0; k<MODES; k++){
            cr[k]  = fmaf( v, ck[k], cr[k]);     // X += u * e^{-i theta}
            cim[k] = fmaf(-v, sk[k], cim[k]);
            float nc = ck[k]*dc[k] - sk[k]*ds[k];
            sk[k] = fmaf(ck[k], ds[k], sk[k]*dc[k]);
            ck[k] = nc;
        }
    }
    // warp butterfly reduce all 32 quantities
    #pragma unroll
    for (int k=0; k<MODES; k++){
        #pragma unroll
        for (int off=16; off; off>>=1){
            cr[k]  += __shfl_xor_sync(0xffffffffu, cr[k],  off);
            cim[k] += __shfl_xor_sync(0xffffffffu, cim[k], off);
        }
    }
    __shared__ float red[8][MODES*2];
    if (lane == 0){
        #pragma unroll
        for (int k=0; k<MODES; k++){
            red[warp][2*k]   = cr[k];
            red[warp][2*k+1] = cim[k];
        }
    }
    __syncthreads();
    if (tid < MODES*2){
        float s = 0.f;
        #pragma unroll
        for (int w=0; w<8; w++) s += red[w][tid];
        g_part[(bi*FBLK + seg)*(MODES*2) + tid] = s;
    }
}

// ---------------- mix: reduce partials, fold proj into mode weights ----------------
__global__ void mix_kernel(const float* __restrict__ sw_r, const float* __restrict__ sw_i,
                           const float* __restrict__ proj_w)
{
    const int b = blockIdx.x;
    const int t = threadIdx.x;         // 96 = CH*MODES
    const int o = t / MODES, k = t % MODES;
    float Zr = 0.f, Zi = 0.f;
    #pragma unroll
    for (int i=0; i<CH; i++){
        float Xr=0.f, Xi=0.f;
        int bi = b*CH + i;
        #pragma unroll
        for (int s=0; s<FBLK; s++){
            Xr += g_part[(bi*FBLK+s)*(MODES*2) + 2*k];
            Xi += g_part[(bi*FBLK+s)*(MODES*2) + 2*k + 1];
        }
        // W2[i,o,k] = sum_c (sw_r + i sw_i)[i,c,k] * proj_w[o,c]
        float Wr=0.f, Wi=0.f;
        #pragma unroll
        for (int c=0; c<CH; c++){
            float pw = proj_w[o*CH + c];
            Wr = fmaf(sw_r[(i*CH+c)*MODES + k], pw, Wr);
            Wi = fmaf(sw_i[(i*CH+c)*MODES + k], pw, Wi);
        }
        Zr += Xr*Wr - Xi*Wi;
        Zi += Xr*Wi + Xi*Wr;
    }
    float scale = (k==0) ? (1.0f/NPT) : (2.0f/NPT);   // irfft: DC once, others doubled
    g_Z[(b*CH+o)*MODES*2 + 2*k]     = Zr*scale;
    g_Z[(b*CH+o)*MODES*2 + 2*k + 1] = Zi*scale;
}

// ---------------- synthesis: 16-mode irfft + bias ----------------
__global__ void __launch_bounds__(256)
synth_kernel(float* __restrict__ out, const float* __restrict__ proj_b)
{
    const int blk  = blockIdx.x;        // b*8 + seg
    const int b    = blk >> 3, seg = blk & 7;
    const int tid  = threadIdx.x, lane = tid & 31, warp = tid >> 5;
    const int n0   = seg*8192 + warp*1024 + lane;

    __shared__ float zz[CH*MODES*2];
    __shared__ float pb[CH];
    if (tid < CH*MODES*2) zz[tid] = g_Z[b*CH*MODES*2 + tid];
    if (tid < CH)         pb[tid] = proj_b[tid];
    __syncthreads();

    const float TWO_PI = 6.283185307179586f;
    float ck[MODES], sk[MODES], dc[MODES], ds[MODES];
    #pragma unroll
    for (int k=0; k<MODES; k++){
        float a0 = TWO_PI * ((float)((k*n0) & NMASK) * (1.0f/NPT));
        sincosf(a0, &sk[k], &ck[k]);
        float ad = TWO_PI * ((float)(k*32) * (1.0f/NPT));
        sincosf(ad, &ds[k], &dc[k]);
    }
    for (int j=0; j<32; j++){
        int n = n0 + (j<<5);
        float accv[CH];
        #pragma unroll
        for (int o=0; o<CH; o++) accv[o] = pb[o];
        #pragma unroll
        for (int k=0; k<MODES; k++){
            float c = ck[k], s = sk[k];
            #pragma unroll
            for (int o=0; o<CH; o++){
                accv[o] = fmaf( zz[(o*MODES+k)*2],     c, accv[o]);  // Re(Z e^{+i theta})
                accv[o] = fmaf(-zz[(o*MODES+k)*2 + 1], s, accv[o]);
            }
            float nc = c*dc[k] - s*ds[k];
            sk[k] = fmaf(c, ds[k], s*dc[k]);
            ck[k] = nc;
        }
        #pragma unroll
        for (int o=0; o<CH; o++)
            out[((size_t)(b*CH + o))*NPT + n] = accv[o];
    }
}

// ---------------- launch ----------------
extern "C" void kernel_launch(void* const* d_in, const int* in_sizes, int n_in,
                              void* d_out, int out_size)
{
    const float* u0     = (const float*)d_in[0];
    const float* t_span = (const float*)d_in[1];
    const float* conv_w = (const float*)d_in[2];
    const float* conv_b = (const float*)d_in[3];
    const float* sw_r   = (const float*)d_in[4];
    const float* sw_i   = (const float*)d_in[5];
    const float* proj_w = (const float*)d_in[6];
    const float* proj_b = (const float*)d_in[7];
    float* out = (float*)d_out;

    float *bufA = nullptr, *bufB = nullptr;
    cudaGetSymbolAddress((void**)&bufA, g_bufA);
    cudaGetSymbolAddress((void**)&bufB, g_bufB);

    const size_t rk_smem = (size_t)(3*CH*EXT + CH*CH*3 + CH) * sizeof(float);
    cudaFuncSetAttribute(rk4_kernel, cudaFuncAttributeMaxDynamicSharedMemorySize, (int)rk_smem);

    dim3 rkgrid(NPT/TILE, BB);
    const float* src = u0;
    for (int s=0; s<TSTEPS-1; s++){
        float* dstb = (s & 1) ? bufB : bufA;
        rk4_kernel<<<rkgrid, RKTHREADS, rk_smem>>>(src, dstb, t_span, s, conv_w, conv_b);
        src = dstb;
    }
    fwd_dft_kernel<<<BB*CH*FBLK, 256>>>(src);
    mix_kernel<<<BB, CH*MODES>>>(sw_r, sw_i, proj_w);
    synth_kernel<<<BB*8, 256>>>(out, proj_b);
}

// round 2
// speedup vs baseline: 1.0893x; 1.0893x over previous
#include <cuda_runtime.h>

#define CH 6
#define MODES 16
#define BB 32
#define NPT 65536
#define NMASK 65535
#define TSTEPS 8

#define TILE 1024
#define HALO 4
#define EXT (TILE + 2*HALO)      // 1032
#define RKTHREADS 256
#define FBLK 8                   // blocks per (b,i) in forward DFT

// -------- scratch (no allocations allowed) --------
__device__ float g_bufA[BB*CH*NPT];
__device__ float g_bufB[BB*CH*NPT];
__device__ float g_part[BB*CH*FBLK*MODES*2];
__device__ float g_Z[BB*CH*MODES*2];

__device__ __forceinline__ float fast_tanh(float x){
    // accurate to ~1e-6 abs; clamp also sanitizes NaN/Inf garbage from halo slots
    float xc = fminf(fmaxf(x, -9.0f), 9.0f);
    float e  = __expf(2.0f*xc);
    return __fdividef(e - 1.0f, e + 1.0f);
}

// ---------------- RK4 step kernel ----------------
// One kernel = one full RK4 step. u tile in SMEM (loaded once); stage values k
// live in REGISTERS (kr[CH][4] per thread). Neighbor halo k values are
// exchanged via tiny stride-1 smem edge arrays (conflict-free):
//   eL[ci][i] = k at position 4*i   (i=0 sentinel, i=t+1 <- thread t's kr[3])
//   eR[ci][i] = k at position 4*i+1 (i=t <- thread t's kr[0]; i=256 <- tail k(1025))
// Tail positions [1025,1031) handled by tid<6 via ktail[].
// Stage validity shrinks 1/side per stage; combine uses central [4, 1028) only.

template<bool USEK, bool LAST>
__device__ __forceinline__ void stage(
    const float* __restrict__ su,
    float (*eL)[RKTHREADS+4], float (*eR)[RKTHREADS+4],
    float (*ktail)[8],
    const float4* __restrict__ w4, const float* __restrict__ bsh,
    float c, float aw, int gofs, int tid, bool edge,
    float kr[CH][4], float acc[CH][4], float acct[CH])
{
    const int p0 = 4*tid;           // window [p0, p0+6), own points p0+1..p0+4
    float a[CH][4];
    #pragma unroll
    for (int co=0; co<CH; co++){
        a[co][0]=0.f; a[co][1]=0.f; a[co][2]=0.f; a[co][3]=0.f;
    }

    #pragma unroll
    for (int ci=0; ci<CH; ci++){
        const float* ru = su + ci*EXT + p0;
        float4 u0 = *(const float4*)ru;          // conflict-free LDS.128
        float2 u1 = *(const float2*)(ru + 4);    // conflict-free LDS.64
        float xv[6];
        if (USEK){
            xv[0] = fmaf(c, eL[ci][tid],   u0.x);
            xv[1] = fmaf(c, kr[ci][0],     u0.y);
            xv[2] = fmaf(c, kr[ci][1],     u0.z);
            xv[3] = fmaf(c, kr[ci][2],     u0.w);
            xv[4] = fmaf(c, kr[ci][3],     u1.x);
            xv[5] = fmaf(c, eR[ci][tid+1], u1.y);
            if (edge){
                #pragma unroll
                for (int j=0; j<6; j++)
                    if ((unsigned)(gofs + p0 + j) >= NPT) xv[j] = 0.f;
            }
        } else {
            xv[0]=u0.x; xv[1]=u0.y; xv[2]=u0.z; xv[3]=u0.w; xv[4]=u1.x; xv[5]=u1.y;
        }
        #pragma unroll
        for (int co=0; co<CH; co++){
            float4 w = w4[co*CH + ci];           // broadcast LDS.128
            #pragma unroll
            for (int j=0; j<4; j++)
                a[co][j] = fmaf(w.x, xv[j], fmaf(w.y, xv[j+1], fmaf(w.z, xv[j+2], a[co][j])));
        }
    }

    // tail point p = 1025+tid for tid<6
    float ttail[CH];
    if (tid < 6){
        const int p = TILE + 1 + tid;
        #pragma unroll
        for (int co=0; co<CH; co++) ttail[co] = 0.f;
        #pragma unroll
        for (int ci=0; ci<CH; ci++){
            float vv[3];
            #pragma unroll
            for (int t3=0; t3<3; t3++){
                int pp = p - 1 + t3;             // 1024..1031
                float uval = su[ci*EXT + pp];
                float v;
                if (USEK){
                    float kv = (pp == TILE) ? eL[ci][RKTHREADS] : ktail[ci][pp - (TILE+1)];
                    v = fmaf(c, kv, uval);
                } else {
                    v = uval;
                }
                if ((unsigned)(gofs + pp) >= NPT) v = 0.f;
                vv[t3] = v;
            }
            #pragma unroll
            for (int co=0; co<CH; co++){
                float4 w = w4[co*CH + ci];
                ttail[co] = fmaf(w.x, vv[0], fmaf(w.y, vv[1], fmaf(w.z, vv[2], ttail[co])));
            }
        }
    }

    if (!LAST) __syncthreads();     // all reads of old eL/eR/ktail complete

    #pragma unroll
    for (int co=0; co<CH; co++){
        float bias = bsh[co];
        #pragma unroll
        for (int j=0; j<4; j++){
            float t = fast_tanh(a[co][j] + bias);
            kr[co][j] = t;
            if (p0 + 1 + j >= HALO) acc[co][j] = fmaf(aw, t, acc[co][j]);
        }
        if (!LAST){
            eL[co][tid+1] = kr[co][3];
            eR[co][tid]   = kr[co][0];
        }
    }
    if (tid < 6){
        #pragma unroll
        for (int co=0; co<CH; co++){
            float t = fast_tanh(ttail[co] + bsh[co]);
            if (!LAST){
                ktail[co][tid] = t;
                if (tid == 0) eR[co][RKTHREADS] = t;   // k(1025)
            }
            if (tid < 3) acct[co] = fmaf(aw, t, acct[co]);
        }
    }
    if (!LAST) __syncthreads();     // new edge values visible
}

__global__ void __launch_bounds__(RKTHREADS, 2)
rk4_kernel(const float* __restrict__ src, float* __restrict__ dst,
           const float* __restrict__ t_span, int step,
           const float* __restrict__ conv_w, const float* __restrict__ conv_b)
{
    __shared__ float  s_su[CH*EXT];
    __shared__ float  s_eL[CH][RKTHREADS+4];
    __shared__ float  s_eR[CH][RKTHREADS+4];
    __shared__ float  s_kt[CH][8];
    __shared__ float4 s_w4[CH*CH];
    __shared__ float  s_b[CH];

    const int b     = blockIdx.y;
    const int tile0 = blockIdx.x * TILE;
    const int gofs  = tile0 - HALO;
    const int tid   = threadIdx.x;
    const bool edge = (blockIdx.x == 0) | (blockIdx.x == gridDim.x - 1);

    const float dt = t_span[step+1] - t_span[step];

    if (tid < CH*CH)
        s_w4[tid] = make_float4(conv_w[tid*3], conv_w[tid*3+1], conv_w[tid*3+2], 0.f);
    if (tid < CH){
        s_b[tid] = conv_b[tid];
        s_eL[tid][0] = 0.f;          // sentinel: k(0)
        s_kt[tid][6] = 0.f;          // sentinel: k(1031)
        s_kt[tid][7] = 0.f;
    }

    #pragma unroll
    for (int ch=0; ch<CH; ch++){
        const float* sc = src + ((size_t)b*CH + ch)*NPT;
        for (int p=tid; p<EXT; p+=RKTHREADS){
            int g = gofs + p;
            s_su[ch*EXT + p] = ((unsigned)g < NPT) ? sc[g] : 0.f;
        }
    }
    __syncthreads();

    float kr[CH][4], acc[CH][4], acct[CH];
    #pragma unroll
    for (int co=0; co<CH; co++){
        acct[co]=0.f;
        acc[co][0]=0.f; acc[co][1]=0.f; acc[co][2]=0.f; acc[co][3]=0.f;
    }

    stage<false,false>(s_su, s_eL, s_eR, s_kt, s_w4, s_b, 0.f,     1.f, gofs, tid, edge, kr, acc, acct);
    stage<true, false>(s_su, s_eL, s_eR, s_kt, s_w4, s_b, 0.5f*dt, 2.f, gofs, tid, edge, kr, acc, acct);
    stage<true, false>(s_su, s_eL, s_eR, s_kt, s_w4, s_b, 0.5f*dt, 2.f, gofs, tid, edge, kr, acc, acct);
    stage<true, true >(s_su, s_eL, s_eR, s_kt, s_w4, s_b, dt,      1.f, gofs, tid, edge, kr, acc, acct);

    const float dt6 = dt * (1.0f/6.0f);
    const int p0 = 4*tid;
    #pragma unroll
    for (int co=0; co<CH; co++){
        float* dp = dst + ((size_t)b*CH + co)*NPT + gofs;
        const float* ru = s_su + co*EXT + p0;
        float4 u0 = *(const float4*)ru;
        float2 u1 = *(const float2*)(ru + 4);
        float uv[4] = {u0.y, u0.z, u0.w, u1.x};
        #pragma unroll
        for (int j=0; j<4; j++){
            int p = p0 + 1 + j;
            if (p >= HALO) dp[p] = uv[j] + dt6 * acc[co][j];
        }
    }
    if (tid < 3){
        int p = TILE + 1 + tid;      // 1025..1027, central
        #pragma unroll
        for (int co=0; co<CH; co++)
            dst[((size_t)b*CH + co)*NPT + gofs + p] = s_su[co*EXT + p] + dt6 * acct[co];
    }
}

// ---------------- forward 16-mode DFT (partial sums) ----------------
__global__ void __launch_bounds__(256)
fwd_dft_kernel(const float* __restrict__ u)
{
    const int blk  = blockIdx.x;                 // [0, BB*CH*FBLK)
    const int seg  = blk & (FBLK-1);
    const int bi   = blk / FBLK;                 // b*CH + i
    const int tid  = threadIdx.x;
    const int lane = tid & 31, warp = tid >> 5;
    const int n0   = seg*8192 + warp*1024 + lane;  // stride-32 walk, coalesced
    const float* x = u + (size_t)bi*NPT;

    const float TWO_PI = 6.283185307179586f;
    float cr[MODES], cim[MODES], ck[MODES], sk[MODES], dc[MODES], ds[MODES];
    #pragma unroll
    for (int k=0; k<MODES; k++){
        cr[k]=0.f; cim[k]=0.f;
        float a0 = TWO_PI * ((float)((k*n0) & NMASK) * (1.0f/NPT));
        sincosf(a0, &sk[k], &ck[k]);
        float ad = TWO_PI * ((float)(k*32) * (1.0f/NPT));
        sincosf(ad, &ds[k], &dc[k]);
    }
    #pragma unroll 2
    for (int j=0; j<32; j++){
        float v = __ldg(&x[n0 + (j<<5)]);
        #pragma unroll
        for (int k=0; k<MODES; k++){
            cr[k]  = fmaf( v, ck[k], cr[k]);     // X += u * e^{-i theta}
            cim[k] = fmaf(-v, sk[k], cim[k]);
            float nc = ck[k]*dc[k] - sk[k]*ds[k];
            sk[k] = fmaf(ck[k], ds[k], sk[k]*dc[k]);
            ck[k] = nc;
        }
    }
    #pragma unroll
    for (int k=0; k<MODES; k++){
        #pragma unroll
        for (int off=16; off; off>>=1){
            cr[k]  += __shfl_xor_sync(0xffffffffu, cr[k],  off);
            cim[k] += __shfl_xor_sync(0xffffffffu, cim[k], off);
        }
    }
    __shared__ float red[8][MODES*2];
    if (lane == 0){
        #pragma unroll
        for (int k=0; k<MODES; k++){
            red[warp][2*k]   = cr[k];
            red[warp][2*k+1] = cim[k];
        }
    }
    __syncthreads();
    if (tid < MODES*2){
        float s = 0.f;
        #pragma unroll
        for (int w=0; w<8; w++) s += red[w][tid];
        g_part[(bi*FBLK + seg)*(MODES*2) + tid] = s;
    }
}

// ---------------- mix: reduce partials, fold proj into mode weights ----------------
__global__ void mix_kernel(const float* __restrict__ sw_r, const float* __restrict__ sw_i,
                           const float* __restrict__ proj_w)
{
    const int b = blockIdx.x;
    const int t = threadIdx.x;         // 96 = CH*MODES
    const int o = t / MODES, k = t % MODES;
    float Zr = 0.f, Zi = 0.f;
    #pragma unroll
    for (int i=0; i<CH; i++){
        float Xr=0.f, Xi=0.f;
        int bi = b*CH + i;
        #pragma unroll
        for (int s=0; s<FBLK; s++){
            Xr += g_part[(bi*FBLK+s)*(MODES*2) + 2*k];
            Xi += g_part[(bi*FBLK+s)*(MODES*2) + 2*k + 1];
        }
        float Wr=0.f, Wi=0.f;
        #pragma unroll
        for (int c=0; c<CH; c++){
            float pw = proj_w[o*CH + c];
            Wr = fmaf(sw_r[(i*CH+c)*MODES + k], pw, Wr);
            Wi = fmaf(sw_i[(i*CH+c)*MODES + k], pw, Wi);
        }
        Zr += Xr*Wr - Xi*Wi;
        Zi += Xr*Wi + Xi*Wr;
    }
    float scale = (k==0) ? (1.0f/NPT) : (2.0f/NPT);   // irfft: DC once, others doubled
    g_Z[(b*CH+o)*MODES*2 + 2*k]     = Zr*scale;
    g_Z[(b*CH+o)*MODES*2 + 2*k + 1] = Zi*scale;
}

// ---------------- synthesis: 16-mode irfft + bias ----------------
__global__ void __launch_bounds__(256)
synth_kernel(float* __restrict__ out, const float* __restrict__ proj_b)
{
    const int blk  = blockIdx.x;        // b*8 + seg
    const int b    = blk >> 3, seg = blk & 7;
    const int tid  = threadIdx.x, lane = tid & 31, warp = tid >> 5;
    const int n0   = seg*8192 + warp*1024 + lane;

    __shared__ float zz[CH*MODES*2];
    __shared__ float pb[CH];
    if (tid < CH*MODES*2) zz[tid] = g_Z[b*CH*MODES*2 + tid];
    if (tid < CH)         pb[tid] = proj_b[tid];
    __syncthreads();

    const float TWO_PI = 6.283185307179586f;
    float ck[MODES], sk[MODES], dc[MODES], ds[MODES];
    #pragma unroll
    for (int k=0; k<MODES; k++){
        float a0 = TWO_PI * ((float)((k*n0) & NMASK) * (1.0f/NPT));
        sincosf(a0, &sk[k], &ck[k]);
        float ad = TWO_PI * ((float)(k*32) * (1.0f/NPT));
        sincosf(ad, &ds[k], &dc[k]);
    }
    for (int j=0; j<32; j++){
        int n = n0 + (j<<5);
        float accv[CH];
        #pragma unroll
        for (int o=0; o<CH; o++) accv[o] = pb[o];
        #pragma unroll
        for (int k=0; k<MODES; k++){
            float c = ck[k], s = sk[k];
            #pragma unroll
            for (int o=0; o<CH; o++){
                accv[o] = fmaf( zz[(o*MODES+k)*2],     c, accv[o]);
                accv[o] = fmaf(-zz[(o*MODES+k)*2 + 1], s, accv[o]);
            }
            float nc = c*dc[k] - s*ds[k];
            sk[k] = fmaf(c, ds[k], s*dc[k]);
            ck[k] = nc;
        }
        #pragma unroll
        for (int o=0; o<CH; o++)
            out[((size_t)(b*CH + o))*NPT + n] = accv[o];
    }
}

// ---------------- launch ----------------
extern "C" void kernel_launch(void* const* d_in, const int* in_sizes, int n_in,
                              void* d_out, int out_size)
{
    const float* u0     = (const float*)d_in[0];
    const float* t_span = (const float*)d_in[1];
    const float* conv_w = (const float*)d_in[2];
    const float* conv_b = (const float*)d_in[3];
    const float* sw_r   = (const float*)d_in[4];
    const float* sw_i   = (const float*)d_in[5];
    const float* proj_w = (const float*)d_in[6];
    const float* proj_b = (const float*)d_in[7];
    float* out = (float*)d_out;

    float *bufA = nullptr, *bufB = nullptr;
    cudaGetSymbolAddress((void**)&bufA, g_bufA);
    cudaGetSymbolAddress((void**)&bufB, g_bufB);

    dim3 rkgrid(NPT/TILE, BB);
    const float* src = u0;
    for (int s=0; s<TSTEPS-1; s++){
        float* dstb = (s & 1) ? bufB : bufA;
        rk4_kernel<<<rkgrid, RKTHREADS>>>(src, dstb, t_span, s, conv_w, conv_b);
        src = dstb;
    }
    fwd_dft_kernel<<<BB*CH*FBLK, 256>>>(src);
    mix_kernel<<<BB, CH*MODES>>>(sw_r, sw_i, proj_w);
    synth_kernel<<<BB*8, 256>>>(out, proj_b);
}

// round 3
// speedup vs baseline: 1.2539x; 1.1511x over previous
#include <cuda_runtime.h>

#define CH 6
#define MODES 16
#define BB 32
#define NPT 65536
#define NMASK 65535
#define TSTEPS 8

#define TILE 1024
#define HALO 4
#define EXT (TILE + 2*HALO)      // 1032
#define RKTHREADS 256
#define EDG 260                  // per-channel stride in edge arrays
#define FBLK 8                   // blocks per (b,i) in forward DFT

// -------- scratch (no allocations allowed) --------
__device__ float g_bufA[BB*CH*NPT];
__device__ float g_bufB[BB*CH*NPT];
__device__ float g_part[BB*CH*FBLK*MODES*2];
__device__ float g_Z[BB*CH*MODES*2];

__constant__ float c_w[CH*CH*3];   // [co][ci][3]
__constant__ float c_b[CH];

__device__ __forceinline__ float fast_tanh(float x){
    // tanh = 1 - 2/(e^{2x}+1); ~1e-7 rel err; clamp sanitizes halo garbage
    float xc = fminf(fmaxf(x, -9.0f), 9.0f);
    float e  = __expf(2.0f*xc);
    return 1.0f - __fdividef(2.0f, e + 1.0f);
}

// ---------------- RK4 step kernel ----------------
// u tile window lives in REGISTERS (xu[CH][6], window [p0, p0+6), own points
// p0+1..p0+4). Stage k values in registers kr[CH][4]. Halo k exchanged via
// double-buffered stride-1 smem edge arrays (1 barrier/stage):
//   eL[ci][i] = k(4i)   (i=0 sentinel; thread t writes i=t+1 <- kr[3])
//   eR[ci][i] = k(4i+1) (thread t writes i=t <- kr[0]; i=256 <- tail k(1025))
// Tail positions [1025,1031) by tid<6 via kt[ci][0..5] (+ sentinels 6,7).
// Validity shrinks 1/side/stage; combine uses central [4, 1028) only.

template<int S>
__device__ __forceinline__ void stage(
    const float (&xu)[CH][6],
    const float* __restrict__ eLr, const float* __restrict__ eRr,
    const float* __restrict__ ktr,
    float* __restrict__ eLw, float* __restrict__ eRw, float* __restrict__ ktw,
    const float* __restrict__ su,
    float cc, float aw, int gofs, int tid, bool edge,
    float (&kr)[CH][4], float (&acc)[CH][4], float (&acct)[CH])
{
    const int p0 = 4*tid;
    float a[CH][4];
    #pragma unroll
    for (int co=0; co<CH; co++){ a[co][0]=0.f; a[co][1]=0.f; a[co][2]=0.f; a[co][3]=0.f; }

    #pragma unroll
    for (int ci=0; ci<CH; ci++){
        float xv[6];
        if (S == 0){
            #pragma unroll
            for (int j=0; j<6; j++) xv[j] = xu[ci][j];
        } else {
            xv[0] = fmaf(cc, eLr[ci*EDG + tid],     xu[ci][0]);
            xv[1] = fmaf(cc, kr[ci][0],             xu[ci][1]);
            xv[2] = fmaf(cc, kr[ci][1],             xu[ci][2]);
            xv[3] = fmaf(cc, kr[ci][2],             xu[ci][3]);
            xv[4] = fmaf(cc, kr[ci][3],             xu[ci][4]);
            xv[5] = fmaf(cc, eRr[ci*EDG + tid + 1], xu[ci][5]);
            if (edge){
                #pragma unroll
                for (int j=0; j<6; j++)
                    if ((unsigned)(gofs + p0 + j) >= NPT) xv[j] = 0.f;
            }
        }
        #pragma unroll
        for (int co=0; co<CH; co++){
            const float w0 = c_w[(co*CH+ci)*3 + 0];
            const float w1 = c_w[(co*CH+ci)*3 + 1];
            const float w2 = c_w[(co*CH+ci)*3 + 2];
            #pragma unroll
            for (int j=0; j<4; j++)
                a[co][j] = fmaf(w0, xv[j], fmaf(w1, xv[j+1], fmaf(w2, xv[j+2], a[co][j])));
        }
    }

    // tail point p = 1025+tid for tid<6
    float ttail[CH];
    if (tid < 6){
        const int p = TILE + 1 + tid;
        #pragma unroll
        for (int co=0; co<CH; co++) ttail[co] = 0.f;
        #pragma unroll
        for (int ci=0; ci<CH; ci++){
            float vv[3];
            #pragma unroll
            for (int t3=0; t3<3; t3++){
                int pp = p - 1 + t3;                 // 1024..1031
                float v = su[ci*EXT + pp];
                if (S > 0){
                    float kv = (pp == TILE) ? eLr[ci*EDG + RKTHREADS]
                                            : ktr[ci*8 + (pp - (TILE+1))];
                    v = fmaf(cc, kv, v);
                }
                if ((unsigned)(gofs + pp) >= NPT) v = 0.f;
                vv[t3] = v;
            }
            #pragma unroll
            for (int co=0; co<CH; co++){
                const float w0 = c_w[(co*CH+ci)*3 + 0];
                const float w1 = c_w[(co*CH+ci)*3 + 1];
                const float w2 = c_w[(co*CH+ci)*3 + 2];
                ttail[co] = fmaf(w0, vv[0], fmaf(w1, vv[1], fmaf(w2, vv[2], ttail[co])));
            }
        }
    }

    #pragma unroll
    for (int co=0; co<CH; co++){
        const float bias = c_b[co];
        #pragma unroll
        for (int j=0; j<4; j++){
            float t = fast_tanh(a[co][j] + bias);
            kr[co][j] = t;
            acc[co][j] = fmaf(aw, t, acc[co][j]);   // combine writes are range-guarded
        }
        if (S < 3){
            eLw[co*EDG + tid + 1] = kr[co][3];
            eRw[co*EDG + tid]     = kr[co][0];
        }
    }
    if (tid < 6){
        #pragma unroll
        for (int co=0; co<CH; co++){
            float t = fast_tanh(ttail[co] + c_b[co]);
            if (S < 3){
                ktw[co*8 + tid] = t;
                if (tid == 0) eRw[co*EDG + RKTHREADS] = t;   // k(1025)
            }
            if (tid < 3) acct[co] = fmaf(aw, t, acct[co]);
        }
    }
    if (S < 3) __syncthreads();
}

__global__ void __launch_bounds__(RKTHREADS, 2)
rk4_kernel(const float* __restrict__ src, float* __restrict__ dst,
           const float* __restrict__ t_span, int step)
{
    extern __shared__ float sm[];
    float* s_su = sm;                      // CH*EXT = 6192
    float* s_eL = s_su + CH*EXT;           // 2*CH*EDG = 3120
    float* s_eR = s_eL + 2*CH*EDG;         // 3120
    float* s_kt = s_eR + 2*CH*EDG;         // 2*CH*8 = 96

    const int b     = blockIdx.y;
    const int tile0 = blockIdx.x * TILE;
    const int gofs  = tile0 - HALO;
    const int tid   = threadIdx.x;
    const bool edge = (blockIdx.x == 0) | (blockIdx.x == gridDim.x - 1);
    const float dt  = t_span[step+1] - t_span[step];

    if (tid < CH){
        s_eL[tid*EDG + 0] = 0.f;  s_eL[(CH+tid)*EDG + 0] = 0.f;   // k(0) sentinels
        s_kt[tid*8 + 6] = 0.f;    s_kt[tid*8 + 7] = 0.f;          // k(1031+) sentinels
        s_kt[(CH+tid)*8 + 6] = 0.f; s_kt[(CH+tid)*8 + 7] = 0.f;
    }
    #pragma unroll
    for (int ch=0; ch<CH; ch++){
        const float* sc = src + ((size_t)b*CH + ch)*NPT;
        for (int p=tid; p<EXT; p+=RKTHREADS){
            int g = gofs + p;
            s_su[ch*EXT + p] = ((unsigned)g < NPT) ? sc[g] : 0.f;
        }
    }
    __syncthreads();

    // u window into registers (aligned, conflict-free LDS)
    float xu[CH][6];
    const int p0 = 4*tid;
    #pragma unroll
    for (int ci=0; ci<CH; ci++){
        const float* ru = s_su + ci*EXT + p0;
        float4 u0 = *(const float4*)ru;
        float2 u1 = *(const float2*)(ru + 4);
        xu[ci][0]=u0.x; xu[ci][1]=u0.y; xu[ci][2]=u0.z;
        xu[ci][3]=u0.w; xu[ci][4]=u1.x; xu[ci][5]=u1.y;
    }

    float kr[CH][4], acc[CH][4], acct[CH];
    #pragma unroll
    for (int co=0; co<CH; co++){
        acct[co]=0.f;
        acc[co][0]=0.f; acc[co][1]=0.f; acc[co][2]=0.f; acc[co][3]=0.f;
    }

    float* eL0 = s_eL;            float* eL1 = s_eL + CH*EDG;
    float* eR0 = s_eR;            float* eR1 = s_eR + CH*EDG;
    float* kt0 = s_kt;            float* kt1 = s_kt + CH*8;

    stage<0>(xu, eL0,eR0,kt0, eL0,eR0,kt0, s_su, 0.f,     1.f, gofs, tid, edge, kr, acc, acct);
    stage<1>(xu, eL0,eR0,kt0, eL1,eR1,kt1, s_su, 0.5f*dt, 2.f, gofs, tid, edge, kr, acc, acct);
    stage<2>(xu, eL1,eR1,kt1, eL0,eR0,kt0, s_su, 0.5f*dt, 2.f, gofs, tid, edge, kr, acc, acct);
    stage<3>(xu, eL0,eR0,kt0, eL1,eR1,kt1, s_su, dt,      1.f, gofs, tid, edge, kr, acc, acct);

    const float dt6 = dt * (1.0f/6.0f);
    #pragma unroll
    for (int co=0; co<CH; co++){
        float* dp = dst + ((size_t)b*CH + co)*NPT + gofs;
        #pragma unroll
        for (int j=0; j<4; j++){
            int p = p0 + 1 + j;
            if (p >= HALO) dp[p] = xu[co][1+j] + dt6 * acc[co][j];
        }
    }
    if (tid < 3){
        int p = TILE + 1 + tid;      // 1025..1027, central
        #pragma unroll
        for (int co=0; co<CH; co++)
            dst[((size_t)b*CH + co)*NPT + gofs + p] = s_su[co*EXT + p] + dt6 * acct[co];
    }
}

// ---------------- forward 16-mode DFT (partial sums) ----------------
__global__ void __launch_bounds__(256)
fwd_dft_kernel(const float* __restrict__ u)
{
    const int blk  = blockIdx.x;                 // [0, BB*CH*FBLK)
    const int seg  = blk & (FBLK-1);
    const int bi   = blk / FBLK;                 // b*CH + i
    const int tid  = threadIdx.x;
    const int lane = tid & 31, warp = tid >> 5;
    const int n0   = seg*8192 + warp*1024 + lane;  // stride-32 walk, coalesced
    const float* x = u + (size_t)bi*NPT;

    const float TWO_PI = 6.283185307179586f;
    float cr[MODES], cim[MODES], ck[MODES], sk[MODES], dc[MODES], ds[MODES];
    #pragma unroll
    for (int k=0; k<MODES; k++){
        cr[k]=0.f; cim[k]=0.f;
        float a0 = TWO_PI * ((float)((k*n0) & NMASK) * (1.0f/NPT));
        sincosf(a0, &sk[k], &ck[k]);
        float ad = TWO_PI * ((float)(k*32) * (1.0f/NPT));
        sincosf(ad, &ds[k], &dc[k]);
    }
    #pragma unroll 2
    for (int j=0; j<32; j++){
        float v = __ldg(&x[n0 + (j<<5)]);
        #pragma unroll
        for (int k=0; k<MODES; k++){
            cr[k]  = fmaf( v, ck[k], cr[k]);     // X += u * e^{-i theta}
            cim[k] = fmaf(-v, sk[k], cim[k]);
            float nc = ck[k]*dc[k] - sk[k]*ds[k];
            sk[k] = fmaf(ck[k], ds[k], sk[k]*dc[k]);
            ck[k] = nc;
        }
    }
    #pragma unroll
    for (int k=0; k<MODES; k++){
        #pragma unroll
        for (int off=16; off; off>>=1){
            cr[k]  += __shfl_xor_sync(0xffffffffu, cr[k],  off);
            cim[k] += __shfl_xor_sync(0xffffffffu, cim[k], off);
        }
    }
    __shared__ float red[8][MODES*2];
    if (lane == 0){
        #pragma unroll
        for (int k=0; k<MODES; k++){
            red[warp][2*k]   = cr[k];
            red[warp][2*k+1] = cim[k];
        }
    }
    __syncthreads();
    if (tid < MODES*2){
        float s = 0.f;
        #pragma unroll
        for (int w=0; w<8; w++) s += red[w][tid];
        g_part[(bi*FBLK + seg)*(MODES*2) + tid] = s;
    }
}

// ---------------- mix: reduce partials, fold proj into mode weights ----------------
__global__ void mix_kernel(const float* __restrict__ sw_r, const float* __restrict__ sw_i,
                           const float* __restrict__ proj_w)
{
    const int b = blockIdx.x;
    const int t = threadIdx.x;         // 96 = CH*MODES
    const int o = t / MODES, k = t % MODES;
    float Zr = 0.f, Zi = 0.f;
    #pragma unroll
    for (int i=0; i<CH; i++){
        float Xr=0.f, Xi=0.f;
        int bi = b*CH + i;
        #pragma unroll
        for (int s=0; s<FBLK; s++){
            Xr += g_part[(bi*FBLK+s)*(MODES*2) + 2*k];
            Xi += g_part[(bi*FBLK+s)*(MODES*2) + 2*k + 1];
        }
        float Wr=0.f, Wi=0.f;
        #pragma unroll
        for (int c=0; c<CH; c++){
            float pw = proj_w[o*CH + c];
            Wr = fmaf(sw_r[(i*CH+c)*MODES + k], pw, Wr);
            Wi = fmaf(sw_i[(i*CH+c)*MODES + k], pw, Wi);
        }
        Zr += Xr*Wr - Xi*Wi;
        Zi += Xr*Wi + Xi*Wr;
    }
    float scale = (k==0) ? (1.0f/NPT) : (2.0f/NPT);   // irfft: DC once, others doubled
    g_Z[(b*CH+o)*MODES*2 + 2*k]     = Zr*scale;
    g_Z[(b*CH+o)*MODES*2 + 2*k + 1] = Zi*scale;
}

// ---------------- synthesis: 16-mode irfft + bias ----------------
__global__ void __launch_bounds__(256)
synth_kernel(float* __restrict__ out, const float* __restrict__ proj_b)
{
    const int blk  = blockIdx.x;        // b*8 + seg
    const int b    = blk >> 3, seg = blk & 7;
    const int tid  = threadIdx.x, lane = tid & 31, warp = tid >> 5;
    const int n0   = seg*8192 + warp*1024 + lane;

    __shared__ float zz[CH*MODES*2];
    __shared__ float pb[CH];
    if (tid < CH*MODES*2) zz[tid] = g_Z[b*CH*MODES*2 + tid];
    if (tid < CH)         pb[tid] = proj_b[tid];
    __syncthreads();

    const float TWO_PI = 6.283185307179586f;
    float ck[MODES], sk[MODES], dc[MODES], ds[MODES];
    #pragma unroll
    for (int k=0; k<MODES; k++){
        float a0 = TWO_PI * ((float)((k*n0) & NMASK) * (1.0f/NPT));
        sincosf(a0, &sk[k], &ck[k]);
        float ad = TWO_PI * ((float)(k*32) * (1.0f/NPT));
        sincosf(ad, &ds[k], &dc[k]);
    }
    for (int j=0; j<32; j++){
        int n = n0 + (j<<5);
        float accv[CH];
        #pragma unroll
        for (int o=0; o<CH; o++) accv[o] = pb[o];
        #pragma unroll
        for (int k=0; k<MODES; k++){
            float c = ck[k], s = sk[k];
            #pragma unroll
            for (int o=0; o<CH; o++){
                accv[o] = fmaf( zz[(o*MODES+k)*2],     c, accv[o]);
                accv[o] = fmaf(-zz[(o*MODES+k)*2 + 1], s, accv[o]);
            }
            float nc = c*dc[k] - s*ds[k];
            sk[k] = fmaf(c, ds[k], s*dc[k]);
            ck[k] = nc;
        }
        #pragma unroll
        for (int o=0; o<CH; o++)
            out[((size_t)(b*CH + o))*NPT + n] = accv[o];
    }
}

// ---------------- launch ----------------
extern "C" void kernel_launch(void* const* d_in, const int* in_sizes, int n_in,
                              void* d_out, int out_size)
{
    const float* u0     = (const float*)d_in[0];
    const float* t_span = (const float*)d_in[1];
    const float* conv_w = (const float*)d_in[2];
    const float* conv_b = (const float*)d_in[3];
    const float* sw_r   = (const float*)d_in[4];
    const float* sw_i   = (const float*)d_in[5];
    const float* proj_w = (const float*)d_in[6];
    const float* proj_b = (const float*)d_in[7];
    float* out = (float*)d_out;

    float *bufA = nullptr, *bufB = nullptr;
    cudaGetSymbolAddress((void**)&bufA, g_bufA);
    cudaGetSymbolAddress((void**)&bufB, g_bufB);

    cudaMemcpyToSymbolAsync(c_w, conv_w, CH*CH*3*sizeof(float), 0,
                            cudaMemcpyDeviceToDevice, 0);
    cudaMemcpyToSymbolAsync(c_b, conv_b, CH*sizeof(float), 0,
                            cudaMemcpyDeviceToDevice, 0);

    const int rk_smem = (CH*EXT + 4*CH*EDG + 4*CH*8) * sizeof(float);
    cudaFuncSetAttribute(rk4_kernel, cudaFuncAttributeMaxDynamicSharedMemorySize, rk_smem);

    dim3 rkgrid(NPT/TILE, BB);
    const float* src = u0;
    for (int s=0; s<TSTEPS-1; s++){
        float* dstb = (s & 1) ? bufB : bufA;
        rk4_kernel<<<rkgrid, RKTHREADS, rk_smem>>>(src, dstb, t_span, s);
        src = dstb;
    }
    fwd_dft_kernel<<<BB*CH*FBLK, 256>>>(src);
    mix_kernel<<<BB, CH*MODES>>>(sw_r, sw_i, proj_w);
    synth_kernel<<<BB*8, 256>>>(out, proj_b);
}

// round 4
// speedup vs baseline: 1.4426x; 1.1505x over previous
#include <cuda_runtime.h>

#define CH 6
#define MODES 16
#define BB 32
#define NPT 65536
#define NMASK 65535
#define TSTEPS 8

#define TILE 1024
#define HALO 4
#define EXT (TILE + 2*HALO)      // 1032
#define RKTHREADS 256
#define EDG 260                  // per-channel stride in edge arrays
#define FBLK 8                   // blocks per (b,i) in forward DFT

// -------- scratch (no allocations allowed) --------
__device__ float g_bufA[BB*CH*NPT];
__device__ float g_bufB[BB*CH*NPT];
__device__ float g_part[BB*CH*FBLK*MODES*2];
__device__ float g_Z[BB*CH*MODES*2];

__constant__ float c_w[CH*CH*3];   // [co][ci][3]
__constant__ float c_b[CH];

__device__ __forceinline__ float htanh(float x){
    float y;
    asm("tanh.approx.f32 %0, %1;" : "=f"(y) : "f"(x));
    return y;
}

// ---------------- RK4 step kernel ----------------
// Linearity split: conv(u + c*k) = conv(u) + c*conv(k).
//   cu[co][4] = conv(u) computed once (stage 0 pre-activation), kept in regs.
//   Stages 1-3: a = cu + c*conv(k); k window from regs + smem edge arrays.
// Edge arrays (double-buffered, stride-1, conflict-free), 1 barrier/stage:
//   eL[ci][i] = k(4i)   (i=0 sentinel; thread t writes i=t+1 <- kr[3])
//   eR[ci][i] = k(4i+1) (thread t writes i=t <- kr[0]; i=256 <- tail k(1025))
// Tail positions [1025,1031) handled by tid<6 via kt (full u+ck path on smem).
// Zero-pad masking: u masked at smem load; k masked in xvk for edge blocks.

template<int S>
__device__ __forceinline__ void stage(
    float (&cu)[CH][4],
    const float* __restrict__ eLr, const float* __restrict__ eRr,
    const float* __restrict__ ktr,
    float* __restrict__ eLw, float* __restrict__ eRw, float* __restrict__ ktw,
    const float* __restrict__ su,
    float cc, float aw, int gofs, int tid, bool edge,
    float (&kr)[CH][4], float (&acc)[CH][4], float (&acct)[CH])
{
    const int p0 = 4*tid;
    float a[CH][4];
    #pragma unroll
    for (int co=0; co<CH; co++){ a[co][0]=0.f; a[co][1]=0.f; a[co][2]=0.f; a[co][3]=0.f; }

    if (S == 0){
        // a = conv(u); u window read from smem (masked at load)
        #pragma unroll
        for (int ci=0; ci<CH; ci++){
            const float* ru = su + ci*EXT + p0;
            float4 u0 = *(const float4*)ru;
            float2 u1 = *(const float2*)(ru + 4);
            float xv[6] = {u0.x, u0.y, u0.z, u0.w, u1.x, u1.y};
            #pragma unroll
            for (int co=0; co<CH; co++){
                const float w0 = c_w[(co*CH+ci)*3 + 0];
                const float w1 = c_w[(co*CH+ci)*3 + 1];
                const float w2 = c_w[(co*CH+ci)*3 + 2];
                #pragma unroll
                for (int j=0; j<4; j++)
                    a[co][j] = fmaf(w0, xv[j], fmaf(w1, xv[j+1], fmaf(w2, xv[j+2], a[co][j])));
            }
        }
        #pragma unroll
        for (int co=0; co<CH; co++)
            #pragma unroll
            for (int j=0; j<4; j++) cu[co][j] = a[co][j];
    } else {
        // a = cu + cc * conv(k)
        #pragma unroll
        for (int ci=0; ci<CH; ci++){
            float xvk[6];
            xvk[0] = eLr[ci*EDG + tid];
            xvk[1] = kr[ci][0]; xvk[2] = kr[ci][1];
            xvk[3] = kr[ci][2]; xvk[4] = kr[ci][3];
            xvk[5] = eRr[ci*EDG + tid + 1];
            if (edge){
                #pragma unroll
                for (int j=0; j<6; j++)
                    if ((unsigned)(gofs + p0 + j) >= NPT) xvk[j] = 0.f;
            }
            #pragma unroll
            for (int co=0; co<CH; co++){
                const float w0 = c_w[(co*CH+ci)*3 + 0];
                const float w1 = c_w[(co*CH+ci)*3 + 1];
                const float w2 = c_w[(co*CH+ci)*3 + 2];
                #pragma unroll
                for (int j=0; j<4; j++)
                    a[co][j] = fmaf(w0, xvk[j], fmaf(w1, xvk[j+1], fmaf(w2, xvk[j+2], a[co][j])));
            }
        }
        #pragma unroll
        for (int co=0; co<CH; co++)
            #pragma unroll
            for (int j=0; j<4; j++) a[co][j] = fmaf(cc, a[co][j], cu[co][j]);
    }

    // tail point p = 1025+tid for tid<6 (full u + cc*k path via smem)
    float ttail[CH];
    if (tid < 6){
        const int p = TILE + 1 + tid;
        #pragma unroll
        for (int co=0; co<CH; co++) ttail[co] = 0.f;
        #pragma unroll
        for (int ci=0; ci<CH; ci++){
            float vv[3];
            #pragma unroll
            for (int t3=0; t3<3; t3++){
                int pp = p - 1 + t3;                 // 1024..1031
                float v = su[ci*EXT + pp];
                if (S > 0){
                    float kv = (pp == TILE) ? eLr[ci*EDG + RKTHREADS]
                                            : ktr[ci*8 + (pp - (TILE+1))];
                    v = fmaf(cc, kv, v);
                }
                if ((unsigned)(gofs + pp) >= NPT) v = 0.f;
                vv[t3] = v;
            }
            #pragma unroll
            for (int co=0; co<CH; co++){
                const float w0 = c_w[(co*CH+ci)*3 + 0];
                const float w1 = c_w[(co*CH+ci)*3 + 1];
                const float w2 = c_w[(co*CH+ci)*3 + 2];
                ttail[co] = fmaf(w0, vv[0], fmaf(w1, vv[1], fmaf(w2, vv[2], ttail[co])));
            }
        }
    }

    #pragma unroll
    for (int co=0; co<CH; co++){
        const float bias = c_b[co];
        #pragma unroll
        for (int j=0; j<4; j++){
            float t = htanh(a[co][j] + bias);
            kr[co][j] = t;
            acc[co][j] = fmaf(aw, t, acc[co][j]);
        }
        if (S < 3){
            eLw[co*EDG + tid + 1] = kr[co][3];
            eRw[co*EDG + tid]     = kr[co][0];
        }
    }
    if (tid < 6){
        #pragma unroll
        for (int co=0; co<CH; co++){
            float t = htanh(ttail[co] + c_b[co]);
            if (S < 3){
                ktw[co*8 + tid] = t;
                if (tid == 0) eRw[co*EDG + RKTHREADS] = t;   // k(1025)
            }
            if (tid < 3) acct[co] = fmaf(aw, t, acct[co]);
        }
    }
    if (S < 3) __syncthreads();
}

__global__ void __launch_bounds__(RKTHREADS, 2)
rk4_kernel(const float* __restrict__ src, float* __restrict__ dst,
           const float* __restrict__ t_span, int step)
{
    extern __shared__ float sm[];
    float* s_su = sm;                      // CH*EXT = 6192
    float* s_eL = s_su + CH*EXT;           // 2*CH*EDG
    float* s_eR = s_eL + 2*CH*EDG;
    float* s_kt = s_eR + 2*CH*EDG;         // 2*CH*8

    const int b     = blockIdx.y;
    const int tile0 = blockIdx.x * TILE;
    const int gofs  = tile0 - HALO;
    const int tid   = threadIdx.x;
    const bool edge = (blockIdx.x == 0) | (blockIdx.x == gridDim.x - 1);
    const float dt  = t_span[step+1] - t_span[step];

    if (tid < CH){
        s_eL[tid*EDG + 0] = 0.f;  s_eL[(CH+tid)*EDG + 0] = 0.f;   // k(0) sentinels
        s_kt[tid*8 + 6] = 0.f;    s_kt[tid*8 + 7] = 0.f;          // k(1031+) sentinels
        s_kt[(CH+tid)*8 + 6] = 0.f; s_kt[(CH+tid)*8 + 7] = 0.f;
    }
    #pragma unroll
    for (int ch=0; ch<CH; ch++){
        const float* sc = src + ((size_t)b*CH + ch)*NPT;
        for (int p=tid; p<EXT; p+=RKTHREADS){
            int g = gofs + p;
            s_su[ch*EXT + p] = ((unsigned)g < NPT) ? sc[g] : 0.f;
        }
    }
    __syncthreads();

    float cu[CH][4], kr[CH][4], acc[CH][4], acct[CH];
    #pragma unroll
    for (int co=0; co<CH; co++){
        acct[co]=0.f;
        acc[co][0]=0.f; acc[co][1]=0.f; acc[co][2]=0.f; acc[co][3]=0.f;
    }

    float* eL0 = s_eL;            float* eL1 = s_eL + CH*EDG;
    float* eR0 = s_eR;            float* eR1 = s_eR + CH*EDG;
    float* kt0 = s_kt;            float* kt1 = s_kt + CH*8;

    stage<0>(cu, eL0,eR0,kt0, eL0,eR0,kt0, s_su, 0.f,     1.f, gofs, tid, edge, kr, acc, acct);
    stage<1>(cu, eL0,eR0,kt0, eL1,eR1,kt1, s_su, 0.5f*dt, 2.f, gofs, tid, edge, kr, acc, acct);
    stage<2>(cu, eL1,eR1,kt1, eL0,eR0,kt0, s_su, 0.5f*dt, 2.f, gofs, tid, edge, kr, acc, acct);
    stage<3>(cu, eL0,eR0,kt0, eL1,eR1,kt1, s_su, dt,      1.f, gofs, tid, edge, kr, acc, acct);

    const float dt6 = dt * (1.0f/6.0f);
    const int p0 = 4*tid;
    #pragma unroll
    for (int co=0; co<CH; co++){
        float* dp = dst + ((size_t)b*CH + co)*NPT + gofs;
        const float* ru = s_su + co*EXT + p0;
        float4 u0 = *(const float4*)ru;          // covers p0..p0+3
        float  u4 = ru[4];                        // p0+4
        float uv[4] = {u0.y, u0.z, u0.w, u4};
        #pragma unroll
        for (int j=0; j<4; j++){
            int p = p0 + 1 + j;
            if (p >= HALO) dp[p] = uv[j] + dt6 * acc[co][j];
        }
    }
    if (tid < 3){
        int p = TILE + 1 + tid;      // 1025..1027, central
        #pragma unroll
        for (int co=0; co<CH; co++)
            dst[((size_t)b*CH + co)*NPT + gofs + p] = s_su[co*EXT + p] + dt6 * acct[co];
    }
}

// ---------------- forward 16-mode DFT (partial sums) ----------------
__global__ void __launch_bounds__(256)
fwd_dft_kernel(const float* __restrict__ u)
{
    const int blk  = blockIdx.x;                 // [0, BB*CH*FBLK)
    const int seg  = blk & (FBLK-1);
    const int bi   = blk / FBLK;                 // b*CH + i
    const int tid  = threadIdx.x;
    const int lane = tid & 31, warp = tid >> 5;
    const int n0   = seg*8192 + warp*1024 + lane;  // stride-32 walk, coalesced
    const float* x = u + (size_t)bi*NPT;

    const float TWO_PI = 6.283185307179586f;
    float cr[MODES], cim[MODES], ck[MODES], sk[MODES], dc[MODES], ds[MODES];
    #pragma unroll
    for (int k=0; k<MODES; k++){
        cr[k]=0.f; cim[k]=0.f;
        float a0 = TWO_PI * ((float)((k*n0) & NMASK) * (1.0f/NPT));
        sincosf(a0, &sk[k], &ck[k]);
        float ad = TWO_PI * ((float)(k*32) * (1.0f/NPT));
        sincosf(ad, &ds[k], &dc[k]);
    }
    #pragma unroll 2
    for (int j=0; j<32; j++){
        float v = __ldg(&x[n0 + (j<<5)]);
        #pragma unroll
        for (int k=0; k<MODES; k++){
            cr[k]  = fmaf( v, ck[k], cr[k]);     // X += u * e^{-i theta}
            cim[k] = fmaf(-v, sk[k], cim[k]);
            float nc = ck[k]*dc[k] - sk[k]*ds[k];
            sk[k] = fmaf(ck[k], ds[k], sk[k]*dc[k]);
            ck[k] = nc;
        }
    }
    #pragma unroll
    for (int k=0; k<MODES; k++){
        #pragma unroll
        for (int off=16; off; off>>=1){
            cr[k]  += __shfl_xor_sync(0xffffffffu, cr[k],  off);
            cim[k] += __shfl_xor_sync(0xffffffffu, cim[k], off);
        }
    }
    __shared__ float red[8][MODES*2];
    if (lane == 0){
        #pragma unroll
        for (int k=0; k<MODES; k++){
            red[warp][2*k]   = cr[k];
            red[warp][2*k+1] = cim[k];
        }
    }
    __syncthreads();
    if (tid < MODES*2){
        float s = 0.f;
        #pragma unroll
        for (int w=0; w<8; w++) s += red[w][tid];
        g_part[(bi*FBLK + seg)*(MODES*2) + tid] = s;
    }
}

// ---------------- mix: reduce partials, fold proj into mode weights ----------------
__global__ void mix_kernel(const float* __restrict__ sw_r, const float* __restrict__ sw_i,
                           const float* __restrict__ proj_w)
{
    const int b = blockIdx.x;
    const int t = threadIdx.x;         // 96 = CH*MODES
    const int o = t / MODES, k = t % MODES;
    float Zr = 0.f, Zi = 0.f;
    #pragma unroll
    for (int i=0; i<CH; i++){
        float Xr=0.f, Xi=0.f;
        int bi = b*CH + i;
        #pragma unroll
        for (int s=0; s<FBLK; s++){
            Xr += g_part[(bi*FBLK+s)*(MODES*2) + 2*k];
            Xi += g_part[(bi*FBLK+s)*(MODES*2) + 2*k + 1];
        }
        float Wr=0.f, Wi=0.f;
        #pragma unroll
        for (int c=0; c<CH; c++){
            float pw = proj_w[o*CH + c];
            Wr = fmaf(sw_r[(i*CH+c)*MODES + k], pw, Wr);
            Wi = fmaf(sw_i[(i*CH+c)*MODES + k], pw, Wi);
        }
        Zr += Xr*Wr - Xi*Wi;
        Zi += Xr*Wi + Xi*Wr;
    }
    float scale = (k==0) ? (1.0f/NPT) : (2.0f/NPT);   // irfft: DC once, others doubled
    g_Z[(b*CH+o)*MODES*2 + 2*k]     = Zr*scale;
    g_Z[(b*CH+o)*MODES*2 + 2*k + 1] = Zi*scale;
}

// ---------------- synthesis: 16-mode irfft + bias ----------------
__global__ void __launch_bounds__(256)
synth_kernel(float* __restrict__ out, const float* __restrict__ proj_b)
{
    const int blk  = blockIdx.x;        // b*8 + seg
    const int b    = blk >> 3, seg = blk & 7;
    const int tid  = threadIdx.x, lane = tid & 31, warp = tid >> 5;
    const int n0   = seg*8192 + warp*1024 + lane;

    __shared__ float zz[CH*MODES*2];
    __shared__ float pb[CH];
    if (tid < CH*MODES*2) zz[tid] = g_Z[b*CH*MODES*2 + tid];
    if (tid < CH)         pb[tid] = proj_b[tid];
    __syncthreads();

    const float TWO_PI = 6.283185307179586f;
    float ck[MODES], sk[MODES], dc[MODES], ds[MODES];
    #pragma unroll
    for (int k=0; k<MODES; k++){
        float a0 = TWO_PI * ((float)((k*n0) & NMASK) * (1.0f/NPT));
        sincosf(a0, &sk[k], &ck[k]);
        float ad = TWO_PI * ((float)(k*32) * (1.0f/NPT));
        sincosf(ad, &ds[k], &dc[k]);
    }
    for (int j=0; j<32; j++){
        int n = n0 + (j<<5);
        float accv[CH];
        #pragma unroll
        for (int o=0; o<CH; o++) accv[o] = pb[o];
        #pragma unroll
        for (int k=0; k<MODES; k++){
            float c = ck[k], s = sk[k];
            #pragma unroll
            for (int o=0; o<CH; o++){
                accv[o] = fmaf( zz[(o*MODES+k)*2],     c, accv[o]);
                accv[o] = fmaf(-zz[(o*MODES+k)*2 + 1], s, accv[o]);
            }
            float nc = c*dc[k] - s*ds[k];
            sk[k] = fmaf(c, ds[k], s*dc[k]);
            ck[k] = nc;
        }
        #pragma unroll
        for (int o=0; o<CH; o++)
            out[((size_t)(b*CH + o))*NPT + n] = accv[o];
    }
}

// ---------------- launch ----------------
extern "C" void kernel_launch(void* const* d_in, const int* in_sizes, int n_in,
                              void* d_out, int out_size)
{
    const float* u0     = (const float*)d_in[0];
    const float* t_span = (const float*)d_in[1];
    const float* conv_w = (const float*)d_in[2];
    const float* conv_b = (const float*)d_in[3];
    const float* sw_r   = (const float*)d_in[4];
    const float* sw_i   = (const float*)d_in[5];
    const float* proj_w = (const float*)d_in[6];
    const float* proj_b = (const float*)d_in[7];
    float* out = (float*)d_out;

    float *bufA = nullptr, *bufB = nullptr;
    cudaGetSymbolAddress((void**)&bufA, g_bufA);
    cudaGetSymbolAddress((void**)&bufB, g_bufB);

    cudaMemcpyToSymbolAsync(c_w, conv_w, CH*CH*3*sizeof(float), 0,
                            cudaMemcpyDeviceToDevice, 0);
    cudaMemcpyToSymbolAsync(c_b, conv_b, CH*sizeof(float), 0,
                            cudaMemcpyDeviceToDevice, 0);

    const int rk_smem = (CH*EXT + 4*CH*EDG + 4*CH*8) * sizeof(float);
    cudaFuncSetAttribute(rk4_kernel, cudaFuncAttributeMaxDynamicSharedMemorySize, rk_smem);

    dim3 rkgrid(NPT/TILE, BB);
    const float* src = u0;
    for (int s=0; s<TSTEPS-1; s++){
        float* dstb = (s & 1) ? bufB : bufA;
        rk4_kernel<<<rkgrid, RKTHREADS, rk_smem>>>(src, dstb, t_span, s);
        src = dstb;
    }
    fwd_dft_kernel<<<BB*CH*FBLK, 256>>>(src);
    mix_kernel<<<BB, CH*MODES>>>(sw_r, sw_i, proj_w);
    synth_kernel<<<BB*8, 256>>>(out, proj_b);
}